// round 14
// baseline (speedup 1.0000x reference)
#include <cuda_runtime.h>
#include <math.h>
#include <stddef.h>

#define DIMD   256
#define NBATCH 64
#define NTOK   4096
#define NS     8
#define MROWS  (NBATCH*NS)           // 512
#define NROWS  ((size_t)NBATCH*NTOK) // 262144
#define NCH    16                    // chunks per batch (flash)
#define CROWS  (NTOK/NCH)            // 256 rows per flash block
#define RPW    (CROWS/4)             // 64 rows per warp
#define NGRP   (RPW/2)               // 32 two-row groups per warp
#define SCALE  0.0625f
#define EPSLN  1e-5f
#define SREN   (1.0f + 4096.0f*1e-8f)

typedef unsigned long long ull;

// ------------------------- static device scratch -------------------------
__device__ float2 d_stats[NROWS];
__device__ float  d_PC [NBATCH*NCH*DIMD];
__device__ float  d_PCt[NBATCH*NCH];
__device__ float  d_Cx [NBATCH*DIMD];
__device__ float  d_Ct [NBATCH];
__device__ float  d_PV [(size_t)NBATCH*NCH*NS*DIMD];
__device__ float  d_Pl [NBATCH*NCH*NS];
__device__ float  d_Pt [NBATCH*NCH*NS];
__device__ float  d_Avec[MROWS*DIMD];
__device__ float  d_Bvec[MROWS*DIMD];
__device__ float  d_Mm [DIMD*DIMD];      // transposed: Mm[t][d] = sum_e Wq[e,d]*Wk[e,t]
__device__ float  d_Wihv[3*DIMD*DIMD];
__device__ float  d_S   [MROWS*DIMD];
__device__ float  d_lnb [MROWS*DIMD];
__device__ float  d_Upre[MROWS*DIMD];
__device__ float  d_hff [MROWS*DIMD];
__device__ float  d_gi  [MROWS*3*DIMD];
__device__ float  d_gh  [MROWS*3*DIMD];

// ------------------------- packed f32x2 helpers -------------------------
__device__ __forceinline__ ull pk2(float lo, float hi){
    ull r; asm("mov.b64 %0, {%1, %2};" : "=l"(r) : "f"(lo), "f"(hi)); return r;
}
__device__ __forceinline__ void upk2(float& lo, float& hi, ull v){
    asm("mov.b64 {%0, %1}, %2;" : "=f"(lo), "=f"(hi) : "l"(v));
}
__device__ __forceinline__ ull fma2(ull a, ull b, ull c){
    ull d; asm("fma.rn.f32x2 %0, %1, %2, %3;" : "=l"(d) : "l"(a), "l"(b), "l"(c)); return d;
}
__device__ __forceinline__ ull mul2(ull a, ull b){
    ull d; asm("mul.rn.f32x2 %0, %1, %2;" : "=l"(d) : "l"(a), "l"(b)); return d;
}
__device__ __forceinline__ ull add2(ull a, ull b){
    ull d; asm("add.rn.f32x2 %0, %1, %2;" : "=l"(d) : "l"(a), "l"(b)); return d;
}

__device__ __forceinline__ float wsum(float v){
#pragma unroll
    for (int o = 16; o > 0; o >>= 1) v += __shfl_xor_sync(0xffffffffu, v, o);
    return v;
}

#define SHX(v,o) __shfl_xor_sync(0xffffffffu, (v), (o))

// 8-value XOR-butterfly reduce-scatter (permuted layout), single chain.
__device__ __forceinline__ float bfly8(float p[NS]){
    p[0] += SHX(p[4],16); p[1] += SHX(p[5],16);
    p[2] += SHX(p[6],16); p[3] += SHX(p[7],16);
    p[0] += SHX(p[2],8);  p[1] += SHX(p[3],8);
    p[0] += SHX(p[1],4);
    p[0] += SHX(p[0],2);
    p[0] += SHX(p[0],1);
    return p[0];
}

// Two interleaved butterflies (rows r, r+1).
__device__ __forceinline__ void bfly8x2(float p[NS], float q[NS], float& o0, float& o1){
    p[0] += SHX(p[4],16); q[0] += SHX(q[4],16);
    p[1] += SHX(p[5],16); q[1] += SHX(q[5],16);
    p[2] += SHX(p[6],16); q[2] += SHX(q[6],16);
    p[3] += SHX(p[7],16); q[3] += SHX(q[7],16);
    p[0] += SHX(p[2],8);  q[0] += SHX(q[2],8);
    p[1] += SHX(p[3],8);  q[1] += SHX(q[3],8);
    p[0] += SHX(p[1],4);  q[0] += SHX(q[1],4);
    p[0] += SHX(p[0],2);  q[0] += SHX(q[0],2);
    p[0] += SHX(p[0],1);  q[0] += SHX(q[0],1);
    o0 = p[0]; o1 = q[0];
}

// ---------------- fused setup: precM + precWihv + init ----------------
__global__ void k_setup(const float* __restrict__ Wq, const float* __restrict__ Wk,
                        const float* __restrict__ Wih, const float* __restrict__ Wv,
                        const float* __restrict__ smu, const float* __restrict__ noise,
                        const float* __restrict__ ls){
    int bid = blockIdx.x, t = threadIdx.x;
    if (bid < 256){
        int dd = bid;
        float acc = 0.f;
        for (int e = 0; e < DIMD; e++)
            acc = fmaf(Wq[e*DIMD + dd], Wk[e*DIMD + t], acc);
        d_Mm[t*DIMD + dd] = acc;
    } else if (bid < 1024){
        int j = bid - 256;
        float acc = 0.f;
        for (int d = 0; d < DIMD; d++)
            acc = fmaf(Wih[j*DIMD + d], Wv[d*DIMD + t], acc);
        d_Wihv[j*DIMD + t] = acc;
    } else {
        int m = bid - 1024;
        d_S[m*DIMD + t] = fmaf(noise[m*DIMD + t], __expf(ls[t]), smu[t]);
    }
}

// ---------------- LN of 512 rows (warp per row) ----------------
__global__ void k_lnrow(const float* __restrict__ in, float* __restrict__ out,
                        const float* __restrict__ g, const float* __restrict__ be){
    int w = (blockIdx.x * blockDim.x + threadIdx.x) >> 5;
    int lane = threadIdx.x & 31;
    const float* row = in + (size_t)w*DIMD + lane*8;
    float4 xa = *(const float4*)row;
    float4 xb = *(const float4*)(row + 4);
    float v[8] = {xa.x,xa.y,xa.z,xa.w,xb.x,xb.y,xb.z,xb.w};
    float s = 0.f, q = 0.f;
#pragma unroll
    for (int j = 0; j < 8; j++){ s += v[j]; q = fmaf(v[j], v[j], q); }
    s = wsum(s); q = wsum(q);
    float mu = s * (1.0f/DIMD);
    float rs = rsqrtf(q * (1.0f/DIMD) - mu*mu + EPSLN);
    float* orow = out + (size_t)w*DIMD;
#pragma unroll
    for (int j = 0; j < 8; j++){
        int dd = lane*8 + j;
        orow[dd] = (v[j] - mu)*rs*g[dd] + be[dd];
    }
}

// ---------------- GEMM for Apre, writing Avec/Bvec directly (32x32 tile) ----------------
__global__ void k_gemmA(const float* __restrict__ gin, const float* __restrict__ bein){
    __shared__ float As[16][33];
    __shared__ float Bs[16][33];
    int tid = threadIdx.x;
    int tx = tid & 15, ty = tid >> 4;
    int m0 = blockIdx.y * 32, n0 = blockIdx.x * 32;
    float a00 = 0.f, a01 = 0.f, a10 = 0.f, a11 = 0.f;
    for (int k0 = 0; k0 < DIMD; k0 += 16){
#pragma unroll
        for (int i = 0; i < 2; i++){
            int idx = tid + i*256;
            int kk = idx & 15, mm = idx >> 4;
            As[kk][mm] = d_lnb[(size_t)(m0 + mm)*DIMD + k0 + kk];
            Bs[kk][mm] = d_Mm[(size_t)(n0 + mm)*DIMD + k0 + kk];
        }
        __syncthreads();
#pragma unroll
        for (int kk = 0; kk < 16; kk++){
            float av0 = As[kk][ty*2], av1 = As[kk][ty*2 + 1];
            float bv0 = Bs[kk][tx*2], bv1 = Bs[kk][tx*2 + 1];
            a00 = fmaf(av0, bv0, a00); a01 = fmaf(av0, bv1, a01);
            a10 = fmaf(av1, bv0, a10); a11 = fmaf(av1, bv1, a11);
        }
        __syncthreads();
    }
    int m = m0 + ty*2, n = n0 + tx*2;
    float vals[2][2] = {{a00, a01}, {a10, a11}};
#pragma unroll
    for (int i = 0; i < 2; i++){
#pragma unroll
        for (int j = 0; j < 2; j++){
            float v = vals[i][j];
            size_t o = (size_t)(m + i)*DIMD + n + j;
            d_Avec[o] = SCALE * gin[n + j]  * v;
            d_Bvec[o] = SCALE * bein[n + j] * v;
        }
    }
}

// ---------------- flash pass ----------------
// 128 threads (4 warps), 256 rows per block (64/warp), lane group g = lane>>2 owns slot g.
// Cross-iteration pipeline: iteration n computes weights for group n (2 rows) while
// applying the V-update for group n-1 (kept xpK/wk regs) -> FMA fills SHFL-chain stalls.
template<bool FIRST>
__global__ void __launch_bounds__(128,2) k_flash(const float* __restrict__ x){
    __shared__ float shV[4][NS][DIMD];
    __shared__ float shl[4][NS], sht[4][NS];
    __shared__ float shC[4][DIMD];
    __shared__ float shct[4];

    int b = blockIdx.y, c = blockIdx.x;
    int w = threadIdx.x >> 5, lane = threadIdx.x & 31;
    int g = lane >> 2;

    ull Ap[NS][4];
#pragma unroll
    for (int j = 0; j < NS; j++){
        int s = g ^ j;
        const float* p = d_Avec + (size_t)(b*NS + s)*DIMD + lane*8;
        float4 u0 = *(const float4*)p;
        float4 u1 = *(const float4*)(p + 4);
        Ap[j][0] = pk2(u0.x,u0.y); Ap[j][1] = pk2(u0.z,u0.w);
        Ap[j][2] = pk2(u1.x,u1.y); Ap[j][3] = pk2(u1.z,u1.w);
    }

    float Gs, Bs;
    {
        float qa[NS];
#pragma unroll
        for (int j = 0; j < NS; j++){
            float s = 0.f;
#pragma unroll
            for (int k = 0; k < 4; k++){
                float lo, hi; upk2(lo, hi, Ap[j][k]);
                s += lo + hi;
            }
            qa[j] = s;
        }
        Gs = bfly8(qa);
        float qb[NS];
#pragma unroll
        for (int j = 0; j < NS; j++){
            int s = g ^ j;
            const float* p = d_Bvec + (size_t)(b*NS + s)*DIMD + lane*8;
            float4 u0 = *(const float4*)p;
            float4 u1 = *(const float4*)(p + 4);
            qb[j] = u0.x+u0.y+u0.z+u0.w+u1.x+u1.y+u1.z+u1.w;
        }
        Bs = bfly8(qb);
    }

    ull V[NS][4];
#pragma unroll
    for (int j = 0; j < NS; j++){
#pragma unroll
        for (int k = 0; k < 4; k++) V[j][k] = 0ull;
    }
    float lacc = 0.f, tacc = 0.f;
    ull Cp[4] = {0ull,0ull,0ull,0ull};
    float ct = 0.f;

    size_t nbase = (size_t)b*NTOK + (size_t)c*CROWS + w*RPW;
    const float* xr = x + nbase*DIMD + lane*8;

    // pipeline state: previous group's packed x rows + weights
    ull xpK0[4], xpK1[4];
    float wk0[NS], wk1[NS];
#pragma unroll
    for (int j = 0; j < NS; j++){ wk0[j] = 0.f; wk1[j] = 0.f; }
#pragma unroll
    for (int k = 0; k < 4; k++){ xpK0[k] = 0ull; xpK1[k] = 0ull; }

    // preload group 0
    float4 na0 = *(const float4*)xr;
    float4 nb0 = *(const float4*)(xr + 4);
    float4 na1 = *(const float4*)(xr + DIMD);
    float4 nb1 = *(const float4*)(xr + DIMD + 4);
    float4 sK;
    if (!FIRST) sK = *(const float4*)&d_stats[nbase];

#pragma unroll 2
    for (int n = 0; n < NGRP; n++){
        ull xpN0[4] = { pk2(na0.x,na0.y), pk2(na0.z,na0.w), pk2(nb0.x,nb0.y), pk2(nb0.z,nb0.w) };
        ull xpN1[4] = { pk2(na1.x,na1.y), pk2(na1.z,na1.w), pk2(nb1.x,nb1.y), pk2(nb1.z,nb1.w) };

        // prefetch group n+1
        float4 sN;
        if (n < NGRP - 1){
            const float* nx = xr + (size_t)(2*n + 2)*DIMD;
            na0 = *(const float4*)nx;        nb0 = *(const float4*)(nx + 4);
            na1 = *(const float4*)(nx+DIMD); nb1 = *(const float4*)(nx + DIMD + 4);
            if (!FIRST) sN = *(const float4*)&d_stats[nbase + 2*n + 2];
        }

        float mu0, rs0, mu1, rs1;
        if (FIRST){
            ull sp0 = add2(add2(xpN0[0],xpN0[1]), add2(xpN0[2],xpN0[3]));
            ull qp0 = fma2(xpN0[0],xpN0[0], fma2(xpN0[1],xpN0[1], fma2(xpN0[2],xpN0[2], mul2(xpN0[3],xpN0[3]))));
            ull sp1 = add2(add2(xpN1[0],xpN1[1]), add2(xpN1[2],xpN1[3]));
            ull qp1 = fma2(xpN1[0],xpN1[0], fma2(xpN1[1],xpN1[1], fma2(xpN1[2],xpN1[2], mul2(xpN1[3],xpN1[3]))));
            float za, zb;
            float s0, q0, s1, q1;
            upk2(za, zb, sp0); s0 = za + zb; upk2(za, zb, qp0); q0 = za + zb;
            upk2(za, zb, sp1); s1 = za + zb; upk2(za, zb, qp1); q1 = za + zb;
#pragma unroll
            for (int o = 16; o > 0; o >>= 1){
                s0 += SHX(s0,o); q0 += SHX(q0,o);
                s1 += SHX(s1,o); q1 += SHX(q1,o);
            }
            mu0 = s0*(1.0f/DIMD); rs0 = rsqrtf(q0*(1.0f/DIMD) - mu0*mu0 + EPSLN);
            mu1 = s1*(1.0f/DIMD); rs1 = rsqrtf(q1*(1.0f/DIMD) - mu1*mu1 + EPSLN);
            if (lane == 0)
                *(float4*)&d_stats[nbase + 2*n] = make_float4(mu0, rs0, mu1, rs1);
            ull rp0 = pk2(rs0,rs0), rp1 = pk2(rs1,rs1);
#pragma unroll
            for (int k = 0; k < 4; k++){
                Cp[k] = fma2(rp0, xpN0[k], Cp[k]);
                Cp[k] = fma2(rp1, xpN1[k], Cp[k]);
            }
            ct = fmaf(mu0, rs0, ct);
            ct = fmaf(mu1, rs1, ct);
        } else {
            mu0 = sK.x; rs0 = sK.y; mu1 = sK.z; rs1 = sK.w;
        }

        // dots for group n
        float p0[NS], p1[NS];
#pragma unroll
        for (int j = 0; j < NS; j++){
            ull a0 = fma2(Ap[j][0], xpN0[0], fma2(Ap[j][1], xpN0[1], fma2(Ap[j][2], xpN0[2], mul2(Ap[j][3], xpN0[3]))));
            ull a1 = fma2(Ap[j][0], xpN1[0], fma2(Ap[j][1], xpN1[1], fma2(Ap[j][2], xpN1[2], mul2(Ap[j][3], xpN1[3]))));
            float lo, hi;
            upk2(lo, hi, a0); p0[j] = lo + hi;
            upk2(lo, hi, a1); p1[j] = lo + hi;
        }
        float dot0, dot1;
        bfly8x2(p0, p1, dot0, dot1);

        float murs0 = mu0*rs0, murs1 = mu1*rs1;
        float e0 = __expf(fmaf(rs0, dot0, fmaf(-murs0, Gs, Bs)));
        float e1 = __expf(fmaf(rs1, dot1, fmaf(-murs1, Gs, Bs)));
        lacc += e0 + e1;
        tacc = fmaf(e0, murs0, tacc);
        tacc = fmaf(e1, murs1, tacc);

        // allgather weights (pre-scaled by rs)
        float A0 = e0*rs0,     B0 = e1*rs1;
        float A1 = SHX(A0,4),  B1 = SHX(B0,4);
        float A2 = SHX(A0,8),  B2 = SHX(B0,8);
        float A3 = SHX(A1,8),  B3 = SHX(B1,8);
        float A4 = SHX(A0,16), B4 = SHX(B0,16);
        float A5 = SHX(A1,16), B5 = SHX(B1,16);
        float A6 = SHX(A2,16), B6 = SHX(B2,16);
        float A7 = SHX(A3,16), B7 = SHX(B3,16);
        float wn0[NS] = {A0,A1,A2,A3,A4,A5,A6,A7};
        float wn1[NS] = {B0,B1,B2,B3,B4,B5,B6,B7};

        // V-update for PREVIOUS group (independent of this group's chain)
#pragma unroll
        for (int j = 0; j < NS; j++){
            ull pa = pk2(wk0[j], wk0[j]);
            ull pb = pk2(wk1[j], wk1[j]);
#pragma unroll
            for (int k = 0; k < 4; k++){
                V[j][k] = fma2(pa, xpK0[k], V[j][k]);
                V[j][k] = fma2(pb, xpK1[k], V[j][k]);
            }
        }

        // rotate pipeline state
#pragma unroll
        for (int k = 0; k < 4; k++){ xpK0[k] = xpN0[k]; xpK1[k] = xpN1[k]; }
#pragma unroll
        for (int j = 0; j < NS; j++){ wk0[j] = wn0[j]; wk1[j] = wn1[j]; }
        sK = sN;
    }

    // drain: V-update for the final group
#pragma unroll
    for (int j = 0; j < NS; j++){
        ull pa = pk2(wk0[j], wk0[j]);
        ull pb = pk2(wk1[j], wk1[j]);
#pragma unroll
        for (int k = 0; k < 4; k++){
            V[j][k] = fma2(pa, xpK0[k], V[j][k]);
            V[j][k] = fma2(pb, xpK1[k], V[j][k]);
        }
    }

    // ---------------- epilogue ----------------
#pragma unroll
    for (int j = 0; j < NS; j++){
        int s = g ^ j;
        float2* dst = (float2*)&shV[w][s][lane*8];
#pragma unroll
        for (int k = 0; k < 4; k++){
            float lo, hi; upk2(lo, hi, V[j][k]);
            dst[k] = make_float2(lo, hi);
        }
    }
    if ((lane & 3) == 0){ shl[w][g] = lacc; sht[w][g] = tacc; }
    if (FIRST){
        float2* cd = (float2*)&shC[w][lane*8];
#pragma unroll
        for (int k = 0; k < 4; k++){
            float lo, hi; upk2(lo, hi, Cp[k]);
            cd[k] = make_float2(lo, hi);
        }
        if (lane == 0) shct[w] = ct;
    }
    __syncthreads();

    int t = threadIdx.x;
    size_t pbase = ((size_t)(b*NCH + c)) * NS;
#pragma unroll
    for (int i = 0; i < 16; i++){
        int idx = t + i*128;
        int s = idx >> 8, d = idx & 255;
        float a = shV[0][s][d] + shV[1][s][d] + shV[2][s][d] + shV[3][s][d];
        d_PV[(pbase + s)*DIMD + d] = a;
    }
    if (t < NS){
        d_Pl[pbase + t] = shl[0][t] + shl[1][t] + shl[2][t] + shl[3][t];
        d_Pt[pbase + t] = sht[0][t] + sht[1][t] + sht[2][t] + sht[3][t];
    }
    if (FIRST){
#pragma unroll
        for (int i = 0; i < 2; i++){
            int d = t + i*128;
            d_PC[((size_t)(b*NCH + c))*DIMD + d] =
                shC[0][d] + shC[1][d] + shC[2][d] + shC[3][d];
        }
        if (t == 0)
            d_PCt[b*NCH + c] = shct[0] + shct[1] + shct[2] + shct[3];
    }
}

// ---------------- reduce Cx over chunks (once) ----------------
__global__ void k_redC(){
    int b = blockIdx.x, t = threadIdx.x;
    float a = 0.f;
    for (int c = 0; c < NCH; c++) a += d_PC[((size_t)b*NCH + c)*DIMD + t];
    d_Cx[b*DIMD + t] = a;
    if (t == 0){
        float s = 0.f;
        for (int c = 0; c < NCH; c++) s += d_PCt[b*NCH + c];
        d_Ct[b] = s;
    }
}

// ---------------- combine partials -> Upre ----------------
__global__ void k_combine(const float* __restrict__ gin, const float* __restrict__ bein){
    int m = blockIdx.x, t = threadIdx.x;
    int b = m >> 3, s = m & 7;
    float Z = 0.f, tr = 0.f, Vr = 0.f;
    for (int c = 0; c < NCH; c++){
        size_t pb = ((size_t)(b*NCH + c)) * NS + s;
        Z  += d_Pl[pb];
        tr += d_Pt[pb];
        Vr += d_PV[pb*DIMD + t];
    }
    float invZ = 1.0f / Z;
    float Vn = (Vr*invZ + 1e-8f*d_Cx[b*DIMD + t]) * (1.0f/SREN);
    float tn = (tr*invZ + 1e-8f*d_Ct[b]) * (1.0f/SREN);
    d_Upre[m*DIMD + t] = fmaf(gin[t], Vn - tn, bein[t]);
}

// ---------------- SGEMM: C = act(A @ B^T + bias) (+resid)
// 64x64 tile, 4x4 per thread, 256 threads; optional second problem via blockIdx.z
__global__ void __launch_bounds__(256) k_gemm(
        const float* __restrict__ A, const float* __restrict__ B,
        const float* __restrict__ bias, const float* __restrict__ resid,
        float* __restrict__ C, int Nc, int act,
        const float* __restrict__ A2, const float* __restrict__ B2,
        const float* __restrict__ bias2, float* __restrict__ C2){
    if (blockIdx.z == 1){ A = A2; B = B2; bias = bias2; C = C2; resid = nullptr; }
    __shared__ float As[16][68];
    __shared__ float Bs[16][68];
    int tid = threadIdx.x;
    int tx = tid & 15, ty = tid >> 4;
    int m0 = blockIdx.y * 64, n0 = blockIdx.x * 64;
    int mm = tid >> 2, kk = (tid & 3) * 4;
    float acc[4][4];
#pragma unroll
    for (int i = 0; i < 4; i++)
#pragma unroll
        for (int j = 0; j < 4; j++) acc[i][j] = 0.f;

    for (int k0 = 0; k0 < DIMD; k0 += 16){
        float4 av = *(const float4*)&A[(size_t)(m0 + mm)*DIMD + k0 + kk];
        float4 bv = *(const float4*)&B[(size_t)(n0 + mm)*DIMD + k0 + kk];
        __syncthreads();
        As[kk+0][mm] = av.x; As[kk+1][mm] = av.y; As[kk+2][mm] = av.z; As[kk+3][mm] = av.w;
        Bs[kk+0][mm] = bv.x; Bs[kk+1][mm] = bv.y; Bs[kk+2][mm] = bv.z; Bs[kk+3][mm] = bv.w;
        __syncthreads();
#pragma unroll
        for (int k = 0; k < 16; k++){
            float4 a4 = *(const float4*)&As[k][ty*4];
            float4 b4 = *(const float4*)&Bs[k][tx*4];
            float av_[4] = {a4.x, a4.y, a4.z, a4.w};
            float bv_[4] = {b4.x, b4.y, b4.z, b4.w};
#pragma unroll
            for (int i = 0; i < 4; i++)
#pragma unroll
                for (int j = 0; j < 4; j++)
                    acc[i][j] = fmaf(av_[i], bv_[j], acc[i][j]);
        }
    }

    float4 bias4 = make_float4(0.f,0.f,0.f,0.f);
    if (bias) bias4 = *(const float4*)&bias[n0 + tx*4];
#pragma unroll
    for (int i = 0; i < 4; i++){
        int m = m0 + ty*4 + i;
        float4 o = make_float4(acc[i][0] + bias4.x, acc[i][1] + bias4.y,
                               acc[i][2] + bias4.z, acc[i][3] + bias4.w);
        if (act == 1){
            o.x = fmaxf(o.x, 0.f); o.y = fmaxf(o.y, 0.f);
            o.z = fmaxf(o.z, 0.f); o.w = fmaxf(o.w, 0.f);
        }
        if (resid){
            float4 rv = *(const float4*)&resid[(size_t)m*Nc + n0 + tx*4];
            o.x += rv.x; o.y += rv.y; o.z += rv.z; o.w += rv.w;
        }
        *(float4*)&C[(size_t)m*Nc + n0 + tx*4] = o;
    }
}

// ---------------- GRU gates fused with FF LayerNorm ----------------
__global__ void k_gate_ln(const float* __restrict__ g, const float* __restrict__ be){
    int m = blockIdx.x, t = threadIdx.x;
    const float* gi = d_gi + (size_t)m*768;
    const float* gh = d_gh + (size_t)m*768;
    float ir = gi[t],        hr = gh[t];
    float iz = gi[256 + t],  hz = gh[256 + t];
    float in_ = gi[512 + t], hn = gh[512 + t];
    float r = 1.0f / (1.0f + __expf(-(ir + hr)));
    float z = 1.0f / (1.0f + __expf(-(iz + hz)));
    float nn = tanhf(fmaf(r, hn, in_));
    float hprev = d_S[(size_t)m*DIMD + t];
    float h = fmaf(1.0f - z, nn, z * hprev);
    d_S[(size_t)m*DIMD + t] = h;
    __shared__ float r1[DIMD], r2[DIMD];
    r1[t] = h; r2[t] = h*h;
    __syncthreads();
    for (int o = 128; o > 0; o >>= 1){
        if (t < o){ r1[t] += r1[t+o]; r2[t] += r2[t+o]; }
        __syncthreads();
    }
    float mu = r1[0] * (1.0f/DIMD);
    float rs = rsqrtf(r2[0] * (1.0f/DIMD) - mu*mu + EPSLN);
    d_lnb[(size_t)m*DIMD + t] = (h - mu)*rs*g[t] + be[t];
}

// ---------------- launch ----------------
extern "C" void kernel_launch(void* const* d_in, const int* in_sizes, int n_in,
                              void* d_out, int out_size){
    const float* x      = (const float*)d_in[0];
    const float* noise  = (const float*)d_in[1];
    const float* smu    = (const float*)d_in[2];
    const float* slsig  = (const float*)d_in[3];
    const float* Wq     = (const float*)d_in[4];
    const float* Wk     = (const float*)d_in[5];
    const float* Wv     = (const float*)d_in[6];
    const float* Wih    = (const float*)d_in[7];
    const float* Whh    = (const float*)d_in[8];
    const float* bih    = (const float*)d_in[9];
    const float* bhh    = (const float*)d_in[10];
    const float* W1     = (const float*)d_in[11];
    const float* b1     = (const float*)d_in[12];
    const float* W2     = (const float*)d_in[13];
    const float* b2     = (const float*)d_in[14];
    const float* g_in   = (const float*)d_in[15];
    const float* be_in  = (const float*)d_in[16];
    const float* g_sl   = (const float*)d_in[17];
    const float* be_sl  = (const float*)d_in[18];
    const float* g_ff   = (const float*)d_in[19];
    const float* be_ff  = (const float*)d_in[20];
    float* out = (float*)d_out;

    float *dS, *dLn, *dUpre, *dHff, *dGi, *dGh, *dWihv;
    cudaGetSymbolAddress((void**)&dS,    d_S);
    cudaGetSymbolAddress((void**)&dLn,   d_lnb);
    cudaGetSymbolAddress((void**)&dUpre, d_Upre);
    cudaGetSymbolAddress((void**)&dHff,  d_hff);
    cudaGetSymbolAddress((void**)&dGi,   d_gi);
    cudaGetSymbolAddress((void**)&dGh,   d_gh);
    cudaGetSymbolAddress((void**)&dWihv, d_Wihv);

    k_setup<<<1536, 256>>>(Wq, Wk, Wih, Wv, smu, noise, slsig);

    for (int it = 0; it < 3; it++){
        k_lnrow<<<MROWS/8, 256>>>(dS, dLn, g_sl, be_sl);
        k_gemmA<<<dim3(DIMD/32, MROWS/32), 256>>>(g_in, be_in);
        if (it == 0){
            k_flash<true><<<dim3(NCH, NBATCH), 128>>>(x);
            k_redC<<<NBATCH, DIMD>>>();
        } else {
            k_flash<false><<<dim3(NCH, NBATCH), 128>>>(x);
        }
        k_combine<<<MROWS, DIMD>>>(g_in, be_in);
        // GRU: gi = Upre @ Wihv^T + b_ih ; gh = S @ W_hh^T + b_hh (fused via z)
        k_gemm<<<dim3(768/64, MROWS/64, 2), 256>>>(dUpre, dWihv, bih, nullptr, dGi, 768, 0,
                                                   dS, Whh, bhh, dGh);
        k_gate_ln<<<MROWS, DIMD>>>(g_ff, be_ff);
        // FF
        k_gemm<<<dim3(DIMD/64, MROWS/64, 1), 256>>>(dLn, W1, b1, nullptr, dHff, DIMD, 1,
                                                    nullptr, nullptr, nullptr, nullptr);
        float* dst = (it == 2) ? out : dS;
        k_gemm<<<dim3(DIMD/64, MROWS/64, 1), 256>>>(dHff, W2, b2, dS, dst, DIMD, 0,
                                                    nullptr, nullptr, nullptr, nullptr);
    }
    (void)in_sizes; (void)n_in; (void)out_size;
}

// round 15
// speedup vs baseline: 1.1566x; 1.1566x over previous
#include <cuda_runtime.h>
#include <math.h>
#include <stddef.h>

#define DIMD   256
#define NBATCH 64
#define NTOK   4096
#define NS     8
#define MROWS  (NBATCH*NS)           // 512
#define NROWS  ((size_t)NBATCH*NTOK) // 262144
#define NCH    16                    // chunks per batch (flash)
#define CROWS  (NTOK/NCH)            // 256 rows per flash block
#define RPW    (CROWS/4)             // 64 rows per warp
#define SCALE  0.0625f
#define EPSLN  1e-5f
#define SREN   (1.0f + 4096.0f*1e-8f)

typedef unsigned long long ull;

// ------------------------- static device scratch -------------------------
__device__ float2 d_stats[NROWS];
__device__ float  d_PC [NBATCH*NCH*DIMD];
__device__ float  d_PCt[NBATCH*NCH];
__device__ float  d_Cx [NBATCH*DIMD];
__device__ float  d_Ct [NBATCH];
__device__ float  d_PV [(size_t)NBATCH*NCH*NS*DIMD];
__device__ float  d_Pl [NBATCH*NCH*NS];
__device__ float  d_Pt [NBATCH*NCH*NS];
__device__ float  d_Avec[MROWS*DIMD];
__device__ float  d_Bvec[MROWS*DIMD];
__device__ float  d_Mm [DIMD*DIMD];      // transposed: Mm[t][d] = sum_e Wq[e,d]*Wk[e,t]
__device__ float  d_Wihv[3*DIMD*DIMD];
__device__ float  d_S   [MROWS*DIMD];
__device__ float  d_lnb [MROWS*DIMD];
__device__ float  d_Upre[MROWS*DIMD];
__device__ float  d_hff [MROWS*DIMD];
__device__ float  d_gi  [MROWS*3*DIMD];
__device__ float  d_gh  [MROWS*3*DIMD];

// ------------------------- packed f32x2 helpers -------------------------
__device__ __forceinline__ ull pk2(float lo, float hi){
    ull r; asm("mov.b64 %0, {%1, %2};" : "=l"(r) : "f"(lo), "f"(hi)); return r;
}
__device__ __forceinline__ void upk2(float& lo, float& hi, ull v){
    asm("mov.b64 {%0, %1}, %2;" : "=f"(lo), "=f"(hi) : "l"(v));
}
__device__ __forceinline__ ull fma2(ull a, ull b, ull c){
    ull d; asm("fma.rn.f32x2 %0, %1, %2, %3;" : "=l"(d) : "l"(a), "l"(b), "l"(c)); return d;
}
__device__ __forceinline__ ull mul2(ull a, ull b){
    ull d; asm("mul.rn.f32x2 %0, %1, %2;" : "=l"(d) : "l"(a), "l"(b)); return d;
}
__device__ __forceinline__ ull add2(ull a, ull b){
    ull d; asm("add.rn.f32x2 %0, %1, %2;" : "=l"(d) : "l"(a), "l"(b)); return d;
}

__device__ __forceinline__ float wsum(float v){
#pragma unroll
    for (int o = 16; o > 0; o >>= 1) v += __shfl_xor_sync(0xffffffffu, v, o);
    return v;
}

#define SHX(v,o) __shfl_xor_sync(0xffffffffu, (v), (o))

// 8-value XOR-butterfly reduce-scatter (permuted layout), single chain.
__device__ __forceinline__ float bfly8(float p[NS]){
    p[0] += SHX(p[4],16); p[1] += SHX(p[5],16);
    p[2] += SHX(p[6],16); p[3] += SHX(p[7],16);
    p[0] += SHX(p[2],8);  p[1] += SHX(p[3],8);
    p[0] += SHX(p[1],4);
    p[0] += SHX(p[0],2);
    p[0] += SHX(p[0],1);
    return p[0];
}

// Four interleaved butterflies (rows r..r+3).
__device__ __forceinline__ void bfly8x4(float p[NS], float q[NS], float u[NS], float v[NS],
                                        float& o0, float& o1, float& o2, float& o3){
    p[0]+=SHX(p[4],16); q[0]+=SHX(q[4],16); u[0]+=SHX(u[4],16); v[0]+=SHX(v[4],16);
    p[1]+=SHX(p[5],16); q[1]+=SHX(q[5],16); u[1]+=SHX(u[5],16); v[1]+=SHX(v[5],16);
    p[2]+=SHX(p[6],16); q[2]+=SHX(q[6],16); u[2]+=SHX(u[6],16); v[2]+=SHX(v[6],16);
    p[3]+=SHX(p[7],16); q[3]+=SHX(q[7],16); u[3]+=SHX(u[7],16); v[3]+=SHX(v[7],16);
    p[0]+=SHX(p[2],8);  q[0]+=SHX(q[2],8);  u[0]+=SHX(u[2],8);  v[0]+=SHX(v[2],8);
    p[1]+=SHX(p[3],8);  q[1]+=SHX(q[3],8);  u[1]+=SHX(u[3],8);  v[1]+=SHX(v[3],8);
    p[0]+=SHX(p[1],4);  q[0]+=SHX(q[1],4);  u[0]+=SHX(u[1],4);  v[0]+=SHX(v[1],4);
    p[0]+=SHX(p[0],2);  q[0]+=SHX(q[0],2);  u[0]+=SHX(u[0],2);  v[0]+=SHX(v[0],2);
    p[0]+=SHX(p[0],1);  q[0]+=SHX(q[0],1);  u[0]+=SHX(u[0],1);  v[0]+=SHX(v[0],1);
    o0 = p[0]; o1 = q[0]; o2 = u[0]; o3 = v[0];
}

// ---------------- fused setup: precM + precWihv + init ----------------
__global__ void k_setup(const float* __restrict__ Wq, const float* __restrict__ Wk,
                        const float* __restrict__ Wih, const float* __restrict__ Wv,
                        const float* __restrict__ smu, const float* __restrict__ noise,
                        const float* __restrict__ ls){
    int bid = blockIdx.x, t = threadIdx.x;
    if (bid < 256){
        int dd = bid;
        float acc = 0.f;
        for (int e = 0; e < DIMD; e++)
            acc = fmaf(Wq[e*DIMD + dd], Wk[e*DIMD + t], acc);
        d_Mm[t*DIMD + dd] = acc;
    } else if (bid < 1024){
        int j = bid - 256;
        float acc = 0.f;
        for (int d = 0; d < DIMD; d++)
            acc = fmaf(Wih[j*DIMD + d], Wv[d*DIMD + t], acc);
        d_Wihv[j*DIMD + t] = acc;
    } else {
        int m = bid - 1024;
        d_S[m*DIMD + t] = fmaf(noise[m*DIMD + t], __expf(ls[t]), smu[t]);
    }
}

// ---------------- fused slot-LN + GEMM -> Avec/Bvec (32x32 tile) ----------------
// Block (n0, m0): LN the 32 S-rows in-block (smem), then Apre = LN @ Mm^T tile.
__global__ void __launch_bounds__(256) k_gemmA2(
        const float* __restrict__ gsl, const float* __restrict__ besl,
        const float* __restrict__ gin, const float* __restrict__ bein){
    __shared__ float Sln[32][DIMD + 4];
    __shared__ float Bs[16][33];
    int tid = threadIdx.x;
    int tx = tid & 15, ty = tid >> 4;
    int wz = tid >> 5, lane = tid & 31;
    int m0 = blockIdx.y * 32, n0 = blockIdx.x * 32;

    // in-block LN of rows m0..m0+31 (warp wz handles rows wz*4..wz*4+3)
#pragma unroll
    for (int r4 = 0; r4 < 4; r4++){
        int r = wz*4 + r4;
        const float* row = d_S + (size_t)(m0 + r)*DIMD + lane*8;
        float4 xa = *(const float4*)row;
        float4 xb = *(const float4*)(row + 4);
        float v[8] = {xa.x,xa.y,xa.z,xa.w,xb.x,xb.y,xb.z,xb.w};
        float s = 0.f, q = 0.f;
#pragma unroll
        for (int j = 0; j < 8; j++){ s += v[j]; q = fmaf(v[j], v[j], q); }
        s = wsum(s); q = wsum(q);
        float mu = s * (1.0f/DIMD);
        float rs = rsqrtf(q * (1.0f/DIMD) - mu*mu + EPSLN);
#pragma unroll
        for (int j = 0; j < 8; j++){
            int dd = lane*8 + j;
            Sln[r][dd] = (v[j] - mu)*rs*gsl[dd] + besl[dd];
        }
    }
    __syncthreads();

    float a00 = 0.f, a01 = 0.f, a10 = 0.f, a11 = 0.f;
    for (int k0 = 0; k0 < DIMD; k0 += 16){
#pragma unroll
        for (int i = 0; i < 2; i++){
            int idx = tid + i*256;
            int kk = idx & 15, mm = idx >> 4;
            Bs[kk][mm] = d_Mm[(size_t)(n0 + mm)*DIMD + k0 + kk];
        }
        __syncthreads();
#pragma unroll
        for (int kk = 0; kk < 16; kk++){
            float av0 = Sln[ty*2][k0 + kk], av1 = Sln[ty*2 + 1][k0 + kk];
            float bv0 = Bs[kk][tx*2], bv1 = Bs[kk][tx*2 + 1];
            a00 = fmaf(av0, bv0, a00); a01 = fmaf(av0, bv1, a01);
            a10 = fmaf(av1, bv0, a10); a11 = fmaf(av1, bv1, a11);
        }
        __syncthreads();
    }
    int m = m0 + ty*2, n = n0 + tx*2;
    float vals[2][2] = {{a00, a01}, {a10, a11}};
#pragma unroll
    for (int i = 0; i < 2; i++){
#pragma unroll
        for (int j = 0; j < 2; j++){
            float v = vals[i][j];
            size_t o = (size_t)(m + i)*DIMD + n + j;
            d_Avec[o] = SCALE * gin[n + j]  * v;
            d_Bvec[o] = SCALE * bein[n + j] * v;
        }
    }
}

// ---------------- flash pass (identical to R13) ----------------
// 128 threads (4 warps), 256 rows per block (64 per warp), lane group g = lane>>2 owns slot g.
// 4-row software pipeline, A+V in registers.
template<bool FIRST>
__global__ void __launch_bounds__(128,2) k_flash(const float* __restrict__ x){
    __shared__ float shV[4][NS][DIMD];
    __shared__ float shl[4][NS], sht[4][NS];
    __shared__ float shC[4][DIMD];
    __shared__ float shct[4];

    int b = blockIdx.y, c = blockIdx.x;
    int w = threadIdx.x >> 5, lane = threadIdx.x & 31;
    int g = lane >> 2;

    ull Ap[NS][4];
#pragma unroll
    for (int j = 0; j < NS; j++){
        int s = g ^ j;
        const float* p = d_Avec + (size_t)(b*NS + s)*DIMD + lane*8;
        float4 u0 = *(const float4*)p;
        float4 u1 = *(const float4*)(p + 4);
        Ap[j][0] = pk2(u0.x,u0.y); Ap[j][1] = pk2(u0.z,u0.w);
        Ap[j][2] = pk2(u1.x,u1.y); Ap[j][3] = pk2(u1.z,u1.w);
    }

    float Gs, Bs;
    {
        float qa[NS];
#pragma unroll
        for (int j = 0; j < NS; j++){
            float s = 0.f;
#pragma unroll
            for (int k = 0; k < 4; k++){
                float lo, hi; upk2(lo, hi, Ap[j][k]);
                s += lo + hi;
            }
            qa[j] = s;
        }
        Gs = bfly8(qa);
        float qb[NS];
#pragma unroll
        for (int j = 0; j < NS; j++){
            int s = g ^ j;
            const float* p = d_Bvec + (size_t)(b*NS + s)*DIMD + lane*8;
            float4 u0 = *(const float4*)p;
            float4 u1 = *(const float4*)(p + 4);
            qb[j] = u0.x+u0.y+u0.z+u0.w+u1.x+u1.y+u1.z+u1.w;
        }
        Bs = bfly8(qb);
    }

    ull V[NS][4];
#pragma unroll
    for (int j = 0; j < NS; j++){
#pragma unroll
        for (int k = 0; k < 4; k++) V[j][k] = 0ull;
    }
    float lacc = 0.f, tacc = 0.f;
    ull Cp[4] = {0ull,0ull,0ull,0ull};
    float ct = 0.f;

    size_t nbase = (size_t)b*NTOK + (size_t)c*CROWS + w*RPW;
    const float* xr = x + nbase*DIMD + lane*8;

    float4 na0 = *(const float4*)xr;
    float4 nb0 = *(const float4*)(xr + 4);
    float4 na1 = *(const float4*)(xr + DIMD);
    float4 nb1 = *(const float4*)(xr + DIMD + 4);
    float4 na2 = *(const float4*)(xr + 2*DIMD);
    float4 nb2 = *(const float4*)(xr + 2*DIMD + 4);
    float4 na3 = *(const float4*)(xr + 3*DIMD);
    float4 nb3 = *(const float4*)(xr + 3*DIMD + 4);
    float4 sA, sB;
    if (!FIRST){
        sA = *(const float4*)&d_stats[nbase];
        sB = *(const float4*)&d_stats[nbase + 2];
    }

    for (int r = 0; r < RPW; r += 4){
        ull xp0[4] = { pk2(na0.x,na0.y), pk2(na0.z,na0.w), pk2(nb0.x,nb0.y), pk2(nb0.z,nb0.w) };
        ull xp1[4] = { pk2(na1.x,na1.y), pk2(na1.z,na1.w), pk2(nb1.x,nb1.y), pk2(nb1.z,nb1.w) };
        ull xp2[4] = { pk2(na2.x,na2.y), pk2(na2.z,na2.w), pk2(nb2.x,nb2.y), pk2(nb2.z,nb2.w) };
        ull xp3[4] = { pk2(na3.x,na3.y), pk2(na3.z,na3.w), pk2(nb3.x,nb3.y), pk2(nb3.z,nb3.w) };

        float mu0, rs0, mu1, rs1, mu2, rs2, mu3, rs3;
        if (!FIRST){
            mu0 = sA.x; rs0 = sA.y; mu1 = sA.z; rs1 = sA.w;
            mu2 = sB.x; rs2 = sB.y; mu3 = sB.z; rs3 = sB.w;
        }

        if (r < RPW - 4){
            const float* nx = xr + (size_t)(r+4)*DIMD;
            na0 = *(const float4*)nx;             nb0 = *(const float4*)(nx + 4);
            na1 = *(const float4*)(nx + DIMD);    nb1 = *(const float4*)(nx + DIMD + 4);
            na2 = *(const float4*)(nx + 2*DIMD);  nb2 = *(const float4*)(nx + 2*DIMD + 4);
            na3 = *(const float4*)(nx + 3*DIMD);  nb3 = *(const float4*)(nx + 3*DIMD + 4);
            if (!FIRST){
                sA = *(const float4*)&d_stats[nbase + r + 4];
                sB = *(const float4*)&d_stats[nbase + r + 6];
            }
        }

        if (FIRST){
            ull sp0 = add2(add2(xp0[0],xp0[1]), add2(xp0[2],xp0[3]));
            ull qp0 = fma2(xp0[0],xp0[0], fma2(xp0[1],xp0[1], fma2(xp0[2],xp0[2], mul2(xp0[3],xp0[3]))));
            ull sp1 = add2(add2(xp1[0],xp1[1]), add2(xp1[2],xp1[3]));
            ull qp1 = fma2(xp1[0],xp1[0], fma2(xp1[1],xp1[1], fma2(xp1[2],xp1[2], mul2(xp1[3],xp1[3]))));
            ull sp2 = add2(add2(xp2[0],xp2[1]), add2(xp2[2],xp2[3]));
            ull qp2 = fma2(xp2[0],xp2[0], fma2(xp2[1],xp2[1], fma2(xp2[2],xp2[2], mul2(xp2[3],xp2[3]))));
            ull sp3 = add2(add2(xp3[0],xp3[1]), add2(xp3[2],xp3[3]));
            ull qp3 = fma2(xp3[0],xp3[0], fma2(xp3[1],xp3[1], fma2(xp3[2],xp3[2], mul2(xp3[3],xp3[3]))));
            float za, zb;
            float s0,q0,s1,q1,s2,q2,s3,q3;
            upk2(za,zb,sp0); s0 = za+zb; upk2(za,zb,qp0); q0 = za+zb;
            upk2(za,zb,sp1); s1 = za+zb; upk2(za,zb,qp1); q1 = za+zb;
            upk2(za,zb,sp2); s2 = za+zb; upk2(za,zb,qp2); q2 = za+zb;
            upk2(za,zb,sp3); s3 = za+zb; upk2(za,zb,qp3); q3 = za+zb;
#pragma unroll
            for (int o = 16; o > 0; o >>= 1){
                s0 += SHX(s0,o); q0 += SHX(q0,o);
                s1 += SHX(s1,o); q1 += SHX(q1,o);
                s2 += SHX(s2,o); q2 += SHX(q2,o);
                s3 += SHX(s3,o); q3 += SHX(q3,o);
            }
            mu0 = s0*(1.0f/DIMD); rs0 = rsqrtf(q0*(1.0f/DIMD) - mu0*mu0 + EPSLN);
            mu1 = s1*(1.0f/DIMD); rs1 = rsqrtf(q1*(1.0f/DIMD) - mu1*mu1 + EPSLN);
            mu2 = s2*(1.0f/DIMD); rs2 = rsqrtf(q2*(1.0f/DIMD) - mu2*mu2 + EPSLN);
            mu3 = s3*(1.0f/DIMD); rs3 = rsqrtf(q3*(1.0f/DIMD) - mu3*mu3 + EPSLN);
            if (lane == 0){
                *(float4*)&d_stats[nbase + r]     = make_float4(mu0, rs0, mu1, rs1);
                *(float4*)&d_stats[nbase + r + 2] = make_float4(mu2, rs2, mu3, rs3);
            }
            ull rp0 = pk2(rs0,rs0), rp1 = pk2(rs1,rs1), rp2 = pk2(rs2,rs2), rp3 = pk2(rs3,rs3);
#pragma unroll
            for (int k = 0; k < 4; k++){
                Cp[k] = fma2(rp0, xp0[k], Cp[k]);
                Cp[k] = fma2(rp1, xp1[k], Cp[k]);
                Cp[k] = fma2(rp2, xp2[k], Cp[k]);
                Cp[k] = fma2(rp3, xp3[k], Cp[k]);
            }
            ct = fmaf(mu0, rs0, ct); ct = fmaf(mu1, rs1, ct);
            ct = fmaf(mu2, rs2, ct); ct = fmaf(mu3, rs3, ct);
        }

        float p0[NS], p1[NS], p2[NS], p3[NS];
#pragma unroll
        for (int j = 0; j < NS; j++){
            ull a0 = fma2(Ap[j][0], xp0[0], fma2(Ap[j][1], xp0[1], fma2(Ap[j][2], xp0[2], mul2(Ap[j][3], xp0[3]))));
            ull a1 = fma2(Ap[j][0], xp1[0], fma2(Ap[j][1], xp1[1], fma2(Ap[j][2], xp1[2], mul2(Ap[j][3], xp1[3]))));
            ull a2 = fma2(Ap[j][0], xp2[0], fma2(Ap[j][1], xp2[1], fma2(Ap[j][2], xp2[2], mul2(Ap[j][3], xp2[3]))));
            ull a3 = fma2(Ap[j][0], xp3[0], fma2(Ap[j][1], xp3[1], fma2(Ap[j][2], xp3[2], mul2(Ap[j][3], xp3[3]))));
            float lo, hi;
            upk2(lo, hi, a0); p0[j] = lo + hi;
            upk2(lo, hi, a1); p1[j] = lo + hi;
            upk2(lo, hi, a2); p2[j] = lo + hi;
            upk2(lo, hi, a3); p3[j] = lo + hi;
        }
        float dot0, dot1, dot2, dot3;
        bfly8x4(p0, p1, p2, p3, dot0, dot1, dot2, dot3);

        float murs0 = mu0*rs0, murs1 = mu1*rs1, murs2 = mu2*rs2, murs3 = mu3*rs3;
        float e0 = __expf(fmaf(rs0, dot0, fmaf(-murs0, Gs, Bs)));
        float e1 = __expf(fmaf(rs1, dot1, fmaf(-murs1, Gs, Bs)));
        float e2 = __expf(fmaf(rs2, dot2, fmaf(-murs2, Gs, Bs)));
        float e3 = __expf(fmaf(rs3, dot3, fmaf(-murs3, Gs, Bs)));
        lacc += e0 + e1 + e2 + e3;
        tacc = fmaf(e0, murs0, tacc); tacc = fmaf(e1, murs1, tacc);
        tacc = fmaf(e2, murs2, tacc); tacc = fmaf(e3, murs3, tacc);

        float A0 = e0*rs0, B0 = e1*rs1, C0 = e2*rs2, D0 = e3*rs3;
        float A1 = SHX(A0,4),  B1 = SHX(B0,4),  C1 = SHX(C0,4),  D1 = SHX(D0,4);
        float A2 = SHX(A0,8),  B2 = SHX(B0,8),  C2 = SHX(C0,8),  D2 = SHX(D0,8);
        float A3 = SHX(A1,8),  B3 = SHX(B1,8),  C3 = SHX(C1,8),  D3 = SHX(D1,8);
        float A4 = SHX(A0,16), B4 = SHX(B0,16), C4 = SHX(C0,16), D4 = SHX(D0,16);
        float A5 = SHX(A1,16), B5 = SHX(B1,16), C5 = SHX(C1,16), D5 = SHX(D1,16);
        float A6 = SHX(A2,16), B6 = SHX(B2,16), C6 = SHX(C2,16), D6 = SHX(D2,16);
        float A7 = SHX(A3,16), B7 = SHX(B3,16), C7 = SHX(C3,16), D7 = SHX(D3,16);
        float wa[NS] = {A0,A1,A2,A3,A4,A5,A6,A7};
        float wb[NS] = {B0,B1,B2,B3,B4,B5,B6,B7};
        float wc[NS] = {C0,C1,C2,C3,C4,C5,C6,C7};
        float wd[NS] = {D0,D1,D2,D3,D4,D5,D6,D7};
#pragma unroll
        for (int j = 0; j < NS; j++){
            ull pa = pk2(wa[j], wa[j]);
            ull pb = pk2(wb[j], wb[j]);
            ull pc = pk2(wc[j], wc[j]);
            ull pd = pk2(wd[j], wd[j]);
#pragma unroll
            for (int k = 0; k < 4; k++){
                V[j][k] = fma2(pa, xp0[k], V[j][k]);
                V[j][k] = fma2(pb, xp1[k], V[j][k]);
                V[j][k] = fma2(pc, xp2[k], V[j][k]);
                V[j][k] = fma2(pd, xp3[k], V[j][k]);
            }
        }
    }

#pragma unroll
    for (int j = 0; j < NS; j++){
        int s = g ^ j;
        float2* dst = (float2*)&shV[w][s][lane*8];
#pragma unroll
        for (int k = 0; k < 4; k++){
            float lo, hi; upk2(lo, hi, V[j][k]);
            dst[k] = make_float2(lo, hi);
        }
    }
    if ((lane & 3) == 0){ shl[w][g] = lacc; sht[w][g] = tacc; }
    if (FIRST){
        float2* cd = (float2*)&shC[w][lane*8];
#pragma unroll
        for (int k = 0; k < 4; k++){
            float lo, hi; upk2(lo, hi, Cp[k]);
            cd[k] = make_float2(lo, hi);
        }
        if (lane == 0) shct[w] = ct;
    }
    __syncthreads();

    int t = threadIdx.x;
    size_t pbase = ((size_t)(b*NCH + c)) * NS;
#pragma unroll
    for (int i = 0; i < 16; i++){
        int idx = t + i*128;
        int s = idx >> 8, d = idx & 255;
        float a = shV[0][s][d] + shV[1][s][d] + shV[2][s][d] + shV[3][s][d];
        d_PV[(pbase + s)*DIMD + d] = a;
    }
    if (t < NS){
        d_Pl[pbase + t] = shl[0][t] + shl[1][t] + shl[2][t] + shl[3][t];
        d_Pt[pbase + t] = sht[0][t] + sht[1][t] + sht[2][t] + sht[3][t];
    }
    if (FIRST){
#pragma unroll
        for (int i = 0; i < 2; i++){
            int d = t + i*128;
            d_PC[((size_t)(b*NCH + c))*DIMD + d] =
                shC[0][d] + shC[1][d] + shC[2][d] + shC[3][d];
        }
        if (t == 0)
            d_PCt[b*NCH + c] = shct[0] + shct[1] + shct[2] + shct[3];
    }
}

// ---------------- reduce Cx over chunks (once) ----------------
__global__ void k_redC(){
    int b = blockIdx.x, t = threadIdx.x;
    float a = 0.f;
    for (int c = 0; c < NCH; c++) a += d_PC[((size_t)b*NCH + c)*DIMD + t];
    d_Cx[b*DIMD + t] = a;
    if (t == 0){
        float s = 0.f;
        for (int c = 0; c < NCH; c++) s += d_PCt[b*NCH + c];
        d_Ct[b] = s;
    }
}

// ---------------- combine partials -> Upre ----------------
__global__ void k_combine(const float* __restrict__ gin, const float* __restrict__ bein){
    int m = blockIdx.x, t = threadIdx.x;
    int b = m >> 3, s = m & 7;
    float Z = 0.f, tr = 0.f, Vr = 0.f;
    for (int c = 0; c < NCH; c++){
        size_t pb = ((size_t)(b*NCH + c)) * NS + s;
        Z  += d_Pl[pb];
        tr += d_Pt[pb];
        Vr += d_PV[pb*DIMD + t];
    }
    float invZ = 1.0f / Z;
    float Vn = (Vr*invZ + 1e-8f*d_Cx[b*DIMD + t]) * (1.0f/SREN);
    float tn = (tr*invZ + 1e-8f*d_Ct[b]) * (1.0f/SREN);
    d_Upre[m*DIMD + t] = fmaf(gin[t], Vn - tn, bein[t]);
}

// ---------------- SGEMM: C = act(A @ B^T + bias) (+resid)
// 64x64 tile, 4x4 per thread, 256 threads; optional second problem via blockIdx.z
__global__ void __launch_bounds__(256) k_gemm(
        const float* __restrict__ A, const float* __restrict__ B,
        const float* __restrict__ bias, const float* __restrict__ resid,
        float* __restrict__ C, int Nc, int act,
        const float* __restrict__ A2, const float* __restrict__ B2,
        const float* __restrict__ bias2, float* __restrict__ C2){
    if (blockIdx.z == 1){ A = A2; B = B2; bias = bias2; C = C2; resid = nullptr; }
    __shared__ float As[16][68];
    __shared__ float Bs[16][68];
    int tid = threadIdx.x;
    int tx = tid & 15, ty = tid >> 4;
    int m0 = blockIdx.y * 64, n0 = blockIdx.x * 64;
    int mm = tid >> 2, kk = (tid & 3) * 4;
    float acc[4][4];
#pragma unroll
    for (int i = 0; i < 4; i++)
#pragma unroll
        for (int j = 0; j < 4; j++) acc[i][j] = 0.f;

    for (int k0 = 0; k0 < DIMD; k0 += 16){
        float4 av = *(const float4*)&A[(size_t)(m0 + mm)*DIMD + k0 + kk];
        float4 bv = *(const float4*)&B[(size_t)(n0 + mm)*DIMD + k0 + kk];
        __syncthreads();
        As[kk+0][mm] = av.x; As[kk+1][mm] = av.y; As[kk+2][mm] = av.z; As[kk+3][mm] = av.w;
        Bs[kk+0][mm] = bv.x; Bs[kk+1][mm] = bv.y; Bs[kk+2][mm] = bv.z; Bs[kk+3][mm] = bv.w;
        __syncthreads();
#pragma unroll
        for (int k = 0; k < 16; k++){
            float4 a4 = *(const float4*)&As[k][ty*4];
            float4 b4 = *(const float4*)&Bs[k][tx*4];
            float av_[4] = {a4.x, a4.y, a4.z, a4.w};
            float bv_[4] = {b4.x, b4.y, b4.z, b4.w};
#pragma unroll
            for (int i = 0; i < 4; i++)
#pragma unroll
                for (int j = 0; j < 4; j++)
                    acc[i][j] = fmaf(av_[i], bv_[j], acc[i][j]);
        }
    }

    float4 bias4 = make_float4(0.f,0.f,0.f,0.f);
    if (bias) bias4 = *(const float4*)&bias[n0 + tx*4];
#pragma unroll
    for (int i = 0; i < 4; i++){
        int m = m0 + ty*4 + i;
        float4 o = make_float4(acc[i][0] + bias4.x, acc[i][1] + bias4.y,
                               acc[i][2] + bias4.z, acc[i][3] + bias4.w);
        if (act == 1){
            o.x = fmaxf(o.x, 0.f); o.y = fmaxf(o.y, 0.f);
            o.z = fmaxf(o.z, 0.f); o.w = fmaxf(o.w, 0.f);
        }
        if (resid){
            float4 rv = *(const float4*)&resid[(size_t)m*Nc + n0 + tx*4];
            o.x += rv.x; o.y += rv.y; o.z += rv.z; o.w += rv.w;
        }
        *(float4*)&C[(size_t)m*Nc + n0 + tx*4] = o;
    }
}

// ---------------- GRU gates fused with FF LayerNorm ----------------
__global__ void k_gate_ln(const float* __restrict__ g, const float* __restrict__ be){
    int m = blockIdx.x, t = threadIdx.x;
    const float* gi = d_gi + (size_t)m*768;
    const float* gh = d_gh + (size_t)m*768;
    float ir = gi[t],        hr = gh[t];
    float iz = gi[256 + t],  hz = gh[256 + t];
    float in_ = gi[512 + t], hn = gh[512 + t];
    float r = 1.0f / (1.0f + __expf(-(ir + hr)));
    float z = 1.0f / (1.0f + __expf(-(iz + hz)));
    float nn = tanhf(fmaf(r, hn, in_));
    float hprev = d_S[(size_t)m*DIMD + t];
    float h = fmaf(1.0f - z, nn, z * hprev);
    d_S[(size_t)m*DIMD + t] = h;
    __shared__ float r1[DIMD], r2[DIMD];
    r1[t] = h; r2[t] = h*h;
    __syncthreads();
    for (int o = 128; o > 0; o >>= 1){
        if (t < o){ r1[t] += r1[t+o]; r2[t] += r2[t+o]; }
        __syncthreads();
    }
    float mu = r1[0] * (1.0f/DIMD);
    float rs = rsqrtf(r2[0] * (1.0f/DIMD) - mu*mu + EPSLN);
    d_lnb[(size_t)m*DIMD + t] = (h - mu)*rs*g[t] + be[t];
}

// ---------------- launch ----------------
extern "C" void kernel_launch(void* const* d_in, const int* in_sizes, int n_in,
                              void* d_out, int out_size){
    const float* x      = (const float*)d_in[0];
    const float* noise  = (const float*)d_in[1];
    const float* smu    = (const float*)d_in[2];
    const float* slsig  = (const float*)d_in[3];
    const float* Wq     = (const float*)d_in[4];
    const float* Wk     = (const float*)d_in[5];
    const float* Wv     = (const float*)d_in[6];
    const float* Wih    = (const float*)d_in[7];
    const float* Whh    = (const float*)d_in[8];
    const float* bih    = (const float*)d_in[9];
    const float* bhh    = (const float*)d_in[10];
    const float* W1     = (const float*)d_in[11];
    const float* b1     = (const float*)d_in[12];
    const float* W2     = (const float*)d_in[13];
    const float* b2     = (const float*)d_in[14];
    const float* g_in   = (const float*)d_in[15];
    const float* be_in  = (const float*)d_in[16];
    const float* g_sl   = (const float*)d_in[17];
    const float* be_sl  = (const float*)d_in[18];
    const float* g_ff   = (const float*)d_in[19];
    const float* be_ff  = (const float*)d_in[20];
    float* out = (float*)d_out;

    float *dS, *dLn, *dUpre, *dHff, *dGi, *dGh, *dWihv;
    cudaGetSymbolAddress((void**)&dS,    d_S);
    cudaGetSymbolAddress((void**)&dLn,   d_lnb);
    cudaGetSymbolAddress((void**)&dUpre, d_Upre);
    cudaGetSymbolAddress((void**)&dHff,  d_hff);
    cudaGetSymbolAddress((void**)&dGi,   d_gi);
    cudaGetSymbolAddress((void**)&dGh,   d_gh);
    cudaGetSymbolAddress((void**)&dWihv, d_Wihv);

    k_setup<<<1536, 256>>>(Wq, Wk, Wih, Wv, smu, noise, slsig);

    for (int it = 0; it < 3; it++){
        // fused slot-LN + Avec/Bvec GEMM
        k_gemmA2<<<dim3(DIMD/32, MROWS/32), 256>>>(g_sl, be_sl, g_in, be_in);
        if (it == 0){
            k_flash<true><<<dim3(NCH, NBATCH), 128>>>(x);
            k_redC<<<NBATCH, DIMD>>>();
        } else {
            k_flash<false><<<dim3(NCH, NBATCH), 128>>>(x);
        }
        k_combine<<<MROWS, DIMD>>>(g_in, be_in);
        // GRU: gi = Upre @ Wihv^T + b_ih ; gh = S @ W_hh^T + b_hh (fused via z)
        k_gemm<<<dim3(768/64, MROWS/64, 2), 256>>>(dUpre, dWihv, bih, nullptr, dGi, 768, 0,
                                                   dS, Whh, bhh, dGh);
        k_gate_ln<<<MROWS, DIMD>>>(g_ff, be_ff);
        // FF
        k_gemm<<<dim3(DIMD/64, MROWS/64, 1), 256>>>(dLn, W1, b1, nullptr, dHff, DIMD, 1,
                                                    nullptr, nullptr, nullptr, nullptr);
        float* dst = (it == 2) ? out : dS;
        k_gemm<<<dim3(DIMD/64, MROWS/64, 1), 256>>>(dHff, W2, b2, dS, dst, DIMD, 0,
                                                    nullptr, nullptr, nullptr, nullptr);
    }
    (void)in_sizes; (void)n_in; (void)out_size;
}